// round 15
// baseline (speedup 1.0000x reference)
#include <cuda_runtime.h>
#include <math.h>

#define BATCH 131072
#define SN 32
#define H1 10
#define H2 6
#define NBLK 1024
#define ROWS_PER_BLK (BATCH / NBLK)   // 128
#define TY 8
#define NPARAM 113   // w1s(10) b1s(10) w(10) ws(10) W2(60) b2(6) w3(6) b3(1)

typedef unsigned long long u64;

// ---- static scratch (no allocations allowed) ----
__device__ float  g_partial[96 * NBLK];   // [stat*32+subnet][block]
__device__ double g_sums[96];
__device__ float  g_mean[SN];
__device__ float  g_rstd[SN];

// ---- packed f32x2 helpers (FFMA2 etc., sm_100+) ----
__device__ __forceinline__ u64 f2pack(float a, float b) {
    u64 r; asm("mov.b64 %0,{%1,%2};" : "=l"(r) : "f"(a), "f"(b)); return r;
}
__device__ __forceinline__ u64 f2dup(float a) {
    u64 r; asm("mov.b64 %0,{%1,%1};" : "=l"(r) : "f"(a)); return r;
}
#define F2UNPACK(v, a, b) asm("mov.b64 {%0,%1},%2;" : "=f"(a), "=f"(b) : "l"(v))
__device__ __forceinline__ u64 fma2(u64 a, u64 b, u64 c) {
    u64 d; asm("fma.rn.f32x2 %0,%1,%2,%3;" : "=l"(d) : "l"(a), "l"(b), "l"(c)); return d;
}
__device__ __forceinline__ u64 mul2(u64 a, u64 b) {
    u64 d; asm("mul.rn.f32x2 %0,%1,%2;" : "=l"(d) : "l"(a), "l"(b)); return d;
}
__device__ __forceinline__ u64 add2(u64 a, u64 b) {
    u64 d; asm("add.rn.f32x2 %0,%1,%2;" : "=l"(d) : "l"(a), "l"(b)); return d;
}

#define MONE2 0xBF800000BF800000ULL
#define TWO2  0x4000000040000000ULL
#define C2LOG2E2 0x4038AA3B4038AA3BULL   // 2*log2(e) duplicated
#define C2LOG2E  2.885390043258667f      // same constant, scalar (fp32-rounded)

// core of packed tanh, input ALREADY scaled by 2*log2(e):
// t = 1 - 2/(2^za + 1). exact +/-1 saturation via ex2 under/overflow.
__device__ __forceinline__ u64 tanh2_pre(u64 zz) {
    float za, zb;
    F2UNPACK(zz, za, zb);
    float ea, eb;
    asm("ex2.approx.f32 %0, %1;" : "=f"(ea) : "f"(za));
    asm("ex2.approx.f32 %0, %1;" : "=f"(eb) : "f"(zb));
    float ra, rb;
    asm("rcp.approx.f32 %0, %1;" : "=f"(ra) : "f"(ea + 1.0f));
    asm("rcp.approx.f32 %0, %1;" : "=f"(rb) : "f"(eb + 1.0f));
    const float ta = fmaf(ra, -2.0f, 1.0f);   // FFMA-imm, rt 1
    const float tb = fmaf(rb, -2.0f, 1.0f);
    return f2pack(ta, tb);
}
__device__ __forceinline__ u64 tanh2(u64 z) {       // unscaled input
    return tanh2_pre(mul2(z, C2LOG2E2));
}

// Sign-flipped derivative algebra (exact):
//   sm  = t^2 - 1;  dm = sm*w (=-d);  cm = (t*sm)*ws (=-c, ws=-2w^2)
//   um/vm accumulate -u/-v;  s2m = t2^2 - 1
//   d2  = s2m * (2*t2*um^2 + vm)  ==  (1-t2^2)*(v - 2*t2*u^2)
__global__ void __launch_bounds__(256, 3) k_forward(
    const float* __restrict__ x,
    const float* __restrict__ W1, const float* __restrict__ b1,
    const float* __restrict__ W2, const float* __restrict__ b2,
    const float* __restrict__ W3, const float* __restrict__ b3,
    float* __restrict__ out)
{
    __shared__ float sp[NPARAM * 32];    // scalar params, [param][subnet] -> conflict-free
    __shared__ float red[3][TY][32];

    const int tx = threadIdx.x;          // subnet
    const int ty = threadIdx.y;
    const int tid = ty * 32 + tx;

    for (int p = tid; p < NPARAM * 32; p += 256) {
        int param = p >> 5, s = p & 31;
        float v;
        if      (param < 10)  v = C2LOG2E * W1[s * 10 + param];            // w1s
        else if (param < 20)  v = C2LOG2E * b1[s * 10 + (param - 10)];     // b1s
        else if (param < 30)  v = W1[s * 10 + (param - 20)];               // w
        else if (param < 40)  { float w = W1[s * 10 + (param - 30)]; v = -2.0f * w * w; } // ws
        else if (param < 100) v = W2[s * 60 + (param - 40)];               // i*6+k
        else if (param < 106) v = b2[s * 6 + (param - 100)];
        else if (param < 112) v = W3[s * 6 + (param - 106)];
        else                  v = b3[s];
        sp[p] = v;
    }
    __syncthreads();

    const float* spx = sp + tx;          // per-lane param base (stride 32)
    u64 acc_o = 0, acc_o2 = 0, acc_g = 0;
    const int row0 = blockIdx.x * ROWS_PER_BLK;

    #pragma unroll 1
    for (int it = 0; it < ROWS_PER_BLK / (TY * 2); ++it) {
        const int row = row0 + (it * TY + ty) * 2;
        const float xa = x[(size_t)row * SN + tx];
        const float xb = x[(size_t)(row + 1) * SN + tx];
        const u64 x2 = f2pack(xa, xb);

        // accumulators: z2 (pre-act), um (= -u), vm (= -v)
        u64 z2[H2], um[H2], vm[H2];
        #pragma unroll
        for (int k = 0; k < H2; ++k) {
            z2[k] = f2dup(spx[(100 + k) * 32]);
            um[k] = 0;  vm[k] = 0;
        }

        #pragma unroll
        for (int i = 0; i < H1; ++i) {
            const float w1s = spx[(0  + i) * 32];       // 2log2e * w
            const float b1s = spx[(10 + i) * 32];       // 2log2e * b
            const float w   = spx[(20 + i) * 32];
            const float ws  = spx[(30 + i) * 32];       // -2*w^2
            const u64 t  = tanh2_pre(fma2(f2dup(w1s), x2, f2dup(b1s)));
            const u64 sm = fma2(t, t, MONE2);           // t^2 - 1
            const u64 dm = mul2(sm, f2dup(w));          // -(1-t^2) w
            const u64 cm = mul2(mul2(t, sm), f2dup(ws));// +2 t (1-t^2) w^2  (= -c)
            #pragma unroll
            for (int k = 0; k < H2; ++k) {
                const u64 w2 = f2dup(spx[(40 + i * 6 + k) * 32]);
                z2[k] = fma2(w2, t,  z2[k]);
                um[k] = fma2(w2, dm, um[k]);
                vm[k] = fma2(w2, cm, vm[k]);
            }
        }

        u64 o = f2dup(spx[112 * 32]);
        u64 g = 0;
        #pragma unroll
        for (int k = 0; k < H2; ++k) {
            const u64 t2  = tanh2(z2[k]);
            const u64 s2m = fma2(t2, t2, MONE2);        // t2^2 - 1
            const u64 uu  = mul2(um[k], um[k]);         // u^2
            const u64 t22 = mul2(t2, TWO2);             // 2*t2
            const u64 d2  = mul2(s2m, fma2(t22, uu, vm[k]));
            const u64 w3  = f2dup(spx[(106 + k) * 32]);
            o = fma2(w3, t2, o);
            g = fma2(w3, d2, g);
        }

        float oa, ob; F2UNPACK(o, oa, ob);
        out[(size_t)row * SN + tx]       = oa;
        out[(size_t)(row + 1) * SN + tx] = ob;
        acc_o  = add2(acc_o, o);
        acc_o2 = fma2(o, o, acc_o2);
        acc_g  = fma2(g, g, acc_g);
    }

    {
        float a, b;
        F2UNPACK(acc_o,  a, b);  red[0][ty][tx] = a + b;
        F2UNPACK(acc_o2, a, b);  red[1][ty][tx] = a + b;
        F2UNPACK(acc_g,  a, b);  red[2][ty][tx] = a + b;
    }
    __syncthreads();
    if (ty < 3) {
        float s = 0.0f;
        #pragma unroll
        for (int j = 0; j < TY; ++j) s += red[ty][j][tx];
        g_partial[(ty * 32 + tx) * NBLK + blockIdx.x] = s;
    }
}

// stage-1: 96 blocks, each tree-reduces one contiguous 1024-float row (deterministic)
__global__ void __launch_bounds__(256) k_reduce()
{
    __shared__ double sd[256];
    const int b = blockIdx.x;            // 0..95 = stat*32 + subnet
    const int t = threadIdx.x;
    const float4 v = ((const float4*)(g_partial + b * NBLK))[t];
    sd[t] = (double)v.x + (double)v.y + (double)v.z + (double)v.w;
    __syncthreads();
    for (int o = 128; o > 0; o >>= 1) {
        if (t < o) sd[t] += sd[t + o];
        __syncthreads();
    }
    if (t == 0) g_sums[b] = sd[0];
}

// stage-2: stats + smooth loss (1 warp)
__global__ void k_stats(float* __restrict__ out, int write_loss)
{
    const int s = threadIdx.x;           // subnet
    const double n   = (double)BATCH;
    const double so  = g_sums[0 * 32 + s];
    const double so2 = g_sums[1 * 32 + s];
    const double sg  = g_sums[2 * 32 + s];
    const double mean = so / n;
    const double var  = so2 / n - mean * mean;
    g_mean[s] = (float)mean;
    g_rstd[s] = (float)(1.0 / sqrt(var + 1e-10));
    double pen = (sg / n) / sqrt(var);
    #pragma unroll
    for (int o = 16; o > 0; o >>= 1)
        pen += __shfl_down_sync(0xffffffffu, pen, o);
    if (s == 0 && write_loss)
        out[(size_t)BATCH * SN] = (float)(0.001 * pen);
}

__global__ void __launch_bounds__(256) k_norm(float* __restrict__ out)
{
    __shared__ float sm[32], sr[32];
    if (threadIdx.x < 32) {
        sm[threadIdx.x] = g_mean[threadIdx.x];
        sr[threadIdx.x] = g_rstd[threadIdx.x];
    }
    __syncthreads();
    const size_t stride = (size_t)1024 * 256 * 4;       // elements per chunk
    const size_t base = ((size_t)blockIdx.x * blockDim.x + threadIdx.x) * 4;

    float4 v0 = *reinterpret_cast<float4*>(out + base + 0 * stride);  // MLP=4
    float4 v1 = *reinterpret_cast<float4*>(out + base + 1 * stride);
    float4 v2 = *reinterpret_cast<float4*>(out + base + 2 * stride);
    float4 v3 = *reinterpret_cast<float4*>(out + base + 3 * stride);
    const int s = (int)(base & 31);                      // stride is multiple of 32

    v0.x = (v0.x - sm[s + 0]) * sr[s + 0];
    v0.y = (v0.y - sm[s + 1]) * sr[s + 1];
    v0.z = (v0.z - sm[s + 2]) * sr[s + 2];
    v0.w = (v0.w - sm[s + 3]) * sr[s + 3];
    v1.x = (v1.x - sm[s + 0]) * sr[s + 0];
    v1.y = (v1.y - sm[s + 1]) * sr[s + 1];
    v1.z = (v1.z - sm[s + 2]) * sr[s + 2];
    v1.w = (v1.w - sm[s + 3]) * sr[s + 3];
    v2.x = (v2.x - sm[s + 0]) * sr[s + 0];
    v2.y = (v2.y - sm[s + 1]) * sr[s + 1];
    v2.z = (v2.z - sm[s + 2]) * sr[s + 2];
    v2.w = (v2.w - sm[s + 3]) * sr[s + 3];
    v3.x = (v3.x - sm[s + 0]) * sr[s + 0];
    v3.y = (v3.y - sm[s + 1]) * sr[s + 1];
    v3.z = (v3.z - sm[s + 2]) * sr[s + 2];
    v3.w = (v3.w - sm[s + 3]) * sr[s + 3];

    *reinterpret_cast<float4*>(out + base + 0 * stride) = v0;
    *reinterpret_cast<float4*>(out + base + 1 * stride) = v1;
    *reinterpret_cast<float4*>(out + base + 2 * stride) = v2;
    *reinterpret_cast<float4*>(out + base + 3 * stride) = v3;
}

extern "C" void kernel_launch(void* const* d_in, const int* in_sizes, int n_in,
                              void* d_out, int out_size)
{
    const float* x  = (const float*)d_in[0];
    const float* W1 = (const float*)d_in[1];
    const float* b1 = (const float*)d_in[2];
    const float* W2 = (const float*)d_in[3];
    const float* b2 = (const float*)d_in[4];
    const float* W3 = (const float*)d_in[5];
    const float* b3 = (const float*)d_in[6];
    float* out = (float*)d_out;

    dim3 blk(32, TY);
    k_forward<<<NBLK, blk>>>(x, W1, b1, W2, b2, W3, b3, out);
    k_reduce<<<96, 256>>>();
    const int write_loss = (out_size > BATCH * SN) ? 1 : 0;
    k_stats<<<1, 32>>>(out, write_loss);
    k_norm<<<1024, 256>>>(out);
}

// round 17
// speedup vs baseline: 1.3501x; 1.3501x over previous
#include <cuda_runtime.h>
#include <math.h>

#define BATCH 131072
#define SN 32
#define H1 10
#define H2 6
#define TY 8
#define NCHUNK 8192                    // 16-row chunks: 131072 / 16
#define NBLKF 456                      // 152 SMs (GB300) x 3 CTAs/SM: one balanced wave
#define NPARAM 103                     // w1(10) b1(10) -2*w1^2(10) W2(60) b2(6) w3(6) b3(1)

typedef unsigned long long u64;

// ---- static scratch (no allocations allowed) ----
__device__ float  g_partial[96 * NBLKF];  // [stat*32+subnet][block]
__device__ double g_sums[96];
__device__ float  g_mean[SN];
__device__ float  g_rstd[SN];

// ---- packed f32x2 helpers (FFMA2 etc., sm_100+) ----
__device__ __forceinline__ u64 f2pack(float a, float b) {
    u64 r; asm("mov.b64 %0,{%1,%2};" : "=l"(r) : "f"(a), "f"(b)); return r;
}
__device__ __forceinline__ u64 f2dup(float a) {
    u64 r; asm("mov.b64 %0,{%1,%1};" : "=l"(r) : "f"(a)); return r;
}
#define F2UNPACK(v, a, b) asm("mov.b64 {%0,%1},%2;" : "=f"(a), "=f"(b) : "l"(v))
__device__ __forceinline__ u64 fma2(u64 a, u64 b, u64 c) {
    u64 d; asm("fma.rn.f32x2 %0,%1,%2,%3;" : "=l"(d) : "l"(a), "l"(b), "l"(c)); return d;
}
__device__ __forceinline__ u64 mul2(u64 a, u64 b) {
    u64 d; asm("mul.rn.f32x2 %0,%1,%2;" : "=l"(d) : "l"(a), "l"(b)); return d;
}
__device__ __forceinline__ u64 add2(u64 a, u64 b) {
    u64 d; asm("add.rn.f32x2 %0,%1,%2;" : "=l"(d) : "l"(a), "l"(b)); return d;
}

#define ONE2  0x3F8000003F800000ULL
#define MONE2 0xBF800000BF800000ULL
#define MTWO2 0xC0000000C0000000ULL
#define C2LOG2E2 0x4038AA3B4038AA3BULL   // 2*log2(e) duplicated

// packed tanh: t = 1 - 2/(e^{2x}+1). per-lane MUFU ex2+rcp (MUFU has headroom),
// minimal fma-pipe ops + lowest register footprint. exact +/-1 saturation via
// ex2 under/overflow behavior; |z| is far from any overflow for this data.
__device__ __forceinline__ u64 tanh2(u64 z) {
    float za, zb;
    F2UNPACK(mul2(z, C2LOG2E2), za, zb);
    float ea, eb;
    asm("ex2.approx.f32 %0, %1;" : "=f"(ea) : "f"(za));
    asm("ex2.approx.f32 %0, %1;" : "=f"(eb) : "f"(zb));
    float ra, rb;
    asm("rcp.approx.f32 %0, %1;" : "=f"(ra) : "f"(ea + 1.0f));
    asm("rcp.approx.f32 %0, %1;" : "=f"(rb) : "f"(eb + 1.0f));
    const float ta = fmaf(ra, -2.0f, 1.0f);   // FFMA-imm, rt 1
    const float tb = fmaf(rb, -2.0f, 1.0f);
    return f2pack(ta, tb);
}

// Body identical to the measured-best R13 kernel; ONLY the outer loop is a
// grid-stride over 16-row chunks so the 456-block grid (3 CTAs x 152 SMs)
// runs one balanced wave instead of a 2.3-wave quantized schedule.
__global__ void __launch_bounds__(256, 3) k_forward(
    const float* __restrict__ x,
    const float* __restrict__ W1, const float* __restrict__ b1,
    const float* __restrict__ W2, const float* __restrict__ b2,
    const float* __restrict__ W3, const float* __restrict__ b3,
    float* __restrict__ out)
{
    __shared__ float sp[NPARAM * 32];    // scalar params, [param][subnet] -> conflict-free
    __shared__ float red[3][TY][32];

    const int tx = threadIdx.x;          // subnet
    const int ty = threadIdx.y;
    const int tid = ty * 32 + tx;

    for (int p = tid; p < NPARAM * 32; p += 256) {
        int param = p >> 5, s = p & 31;
        float v;
        if      (param < 10)  v = W1[s * 10 + param];
        else if (param < 20)  v = b1[s * 10 + (param - 10)];
        else if (param < 30)  { float w = W1[s * 10 + (param - 20)]; v = -2.0f * w * w; }
        else if (param < 90)  v = W2[s * 60 + (param - 30)];          // i*6+k
        else if (param < 96)  v = b2[s * 6 + (param - 90)];
        else if (param < 102) v = W3[s * 6 + (param - 96)];
        else                  v = b3[s];
        sp[p] = v;
    }
    __syncthreads();

    const float* spx = sp + tx;          // per-lane param base (stride 32)
    u64 acc_o = 0, acc_o2 = 0, acc_g = 0;

    #pragma unroll 1
    for (int c = blockIdx.x; c < NCHUNK; c += NBLKF) {
        const int row = c * 16 + ty * 2;
        const float xa = x[(size_t)row * SN + tx];
        const float xb = x[(size_t)(row + 1) * SN + tx];
        const u64 x2 = f2pack(xa, xb);

        // accumulators for layer-2 pre-activations and their 1st/2nd-deriv parts
        u64 z2[H2], u[H2], v[H2];
        #pragma unroll
        for (int k = 0; k < H2; ++k) {
            z2[k] = f2dup(spx[(90 + k) * 32]);
            u[k] = 0;  v[k] = 0;
        }

        #pragma unroll
        for (int i = 0; i < H1; ++i) {
            const float w  = spx[(0  + i) * 32];
            const float bb = spx[(10 + i) * 32];
            const float ws = spx[(20 + i) * 32];        // -2*w^2
            const u64 t  = tanh2(fma2(f2dup(w), x2, f2dup(bb)));
            const u64 tn = mul2(t, MONE2);
            const u64 s  = fma2(tn, t, ONE2);           // 1 - t^2
            const u64 d  = mul2(s, f2dup(w));           // (1-t^2) w
            const u64 c1 = mul2(mul2(t, s), f2dup(ws)); // -2 t (1-t^2) w^2
            #pragma unroll
            for (int k = 0; k < H2; ++k) {
                const u64 w2 = f2dup(spx[(30 + i * 6 + k) * 32]);
                z2[k] = fma2(w2, t, z2[k]);
                u[k]  = fma2(w2, d, u[k]);
                v[k]  = fma2(w2, c1, v[k]);
            }
        }

        u64 o = f2dup(spx[102 * 32]);
        u64 g = 0;
        #pragma unroll
        for (int k = 0; k < H2; ++k) {
            const u64 t2  = tanh2(z2[k]);
            const u64 t2n = mul2(t2, MONE2);
            const u64 s2  = fma2(t2n, t2, ONE2);        // 1 - t2^2
            const u64 uu  = mul2(u[k], u[k]);
            const u64 m2t = mul2(t2, MTWO2);            // -2*t2
            const u64 d2  = mul2(s2, fma2(m2t, uu, v[k]));
            const u64 w3  = f2dup(spx[(96 + k) * 32]);
            o = fma2(w3, t2, o);
            g = fma2(w3, d2, g);
        }

        float oa, ob; F2UNPACK(o, oa, ob);
        out[(size_t)row * SN + tx]       = oa;
        out[(size_t)(row + 1) * SN + tx] = ob;
        acc_o  = add2(acc_o, o);
        acc_o2 = fma2(o, o, acc_o2);
        acc_g  = fma2(g, g, acc_g);
    }

    {
        float a, b;
        F2UNPACK(acc_o,  a, b);  red[0][ty][tx] = a + b;
        F2UNPACK(acc_o2, a, b);  red[1][ty][tx] = a + b;
        F2UNPACK(acc_g,  a, b);  red[2][ty][tx] = a + b;
    }
    __syncthreads();
    if (ty < 3) {
        float s = 0.0f;
        #pragma unroll
        for (int j = 0; j < TY; ++j) s += red[ty][j][tx];
        g_partial[(ty * 32 + tx) * NBLKF + blockIdx.x] = s;
    }
}

// stage-1: 96 blocks, each reduces one row of NBLKF partials (deterministic order)
__global__ void __launch_bounds__(256) k_reduce()
{
    __shared__ double sd[256];
    const int b = blockIdx.x;            // 0..95 = stat*32 + subnet
    const int t = threadIdx.x;
    double s = 0.0;
    for (int i = t; i < NBLKF; i += 256)
        s += (double)g_partial[b * NBLKF + i];
    sd[t] = s;
    __syncthreads();
    for (int o = 128; o > 0; o >>= 1) {
        if (t < o) sd[t] += sd[t + o];
        __syncthreads();
    }
    if (t == 0) g_sums[b] = sd[0];
}

// stage-2: stats + smooth loss (1 warp)
__global__ void k_stats(float* __restrict__ out, int write_loss)
{
    const int s = threadIdx.x;           // subnet
    const double n   = (double)BATCH;
    const double so  = g_sums[0 * 32 + s];
    const double so2 = g_sums[1 * 32 + s];
    const double sg  = g_sums[2 * 32 + s];
    const double mean = so / n;
    const double var  = so2 / n - mean * mean;
    g_mean[s] = (float)mean;
    g_rstd[s] = (float)(1.0 / sqrt(var + 1e-10));
    double pen = (sg / n) / sqrt(var);
    #pragma unroll
    for (int o = 16; o > 0; o >>= 1)
        pen += __shfl_down_sync(0xffffffffu, pen, o);
    if (s == 0 && write_loss)
        out[(size_t)BATCH * SN] = (float)(0.001 * pen);
}

__global__ void __launch_bounds__(256) k_norm(float* __restrict__ out)
{
    __shared__ float sm[32], sr[32];
    if (threadIdx.x < 32) {
        sm[threadIdx.x] = g_mean[threadIdx.x];
        sr[threadIdx.x] = g_rstd[threadIdx.x];
    }
    __syncthreads();
    const size_t stride = (size_t)1024 * 256 * 4;       // elements per chunk
    const size_t base = ((size_t)blockIdx.x * blockDim.x + threadIdx.x) * 4;

    float4 v0 = *reinterpret_cast<float4*>(out + base + 0 * stride);  // MLP=4
    float4 v1 = *reinterpret_cast<float4*>(out + base + 1 * stride);
    float4 v2 = *reinterpret_cast<float4*>(out + base + 2 * stride);
    float4 v3 = *reinterpret_cast<float4*>(out + base + 3 * stride);
    const int s = (int)(base & 31);                      // stride is multiple of 32

    v0.x = (v0.x - sm[s + 0]) * sr[s + 0];
    v0.y = (v0.y - sm[s + 1]) * sr[s + 1];
    v0.z = (v0.z - sm[s + 2]) * sr[s + 2];
    v0.w = (v0.w - sm[s + 3]) * sr[s + 3];
    v1.x = (v1.x - sm[s + 0]) * sr[s + 0];
    v1.y = (v1.y - sm[s + 1]) * sr[s + 1];
    v1.z = (v1.z - sm[s + 2]) * sr[s + 2];
    v1.w = (v1.w - sm[s + 3]) * sr[s + 3];
    v2.x = (v2.x - sm[s + 0]) * sr[s + 0];
    v2.y = (v2.y - sm[s + 1]) * sr[s + 1];
    v2.z = (v2.z - sm[s + 2]) * sr[s + 2];
    v2.w = (v2.w - sm[s + 3]) * sr[s + 3];
    v3.x = (v3.x - sm[s + 0]) * sr[s + 0];
    v3.y = (v3.y - sm[s + 1]) * sr[s + 1];
    v3.z = (v3.z - sm[s + 2]) * sr[s + 2];
    v3.w = (v3.w - sm[s + 3]) * sr[s + 3];

    *reinterpret_cast<float4*>(out + base + 0 * stride) = v0;
    *reinterpret_cast<float4*>(out + base + 1 * stride) = v1;
    *reinterpret_cast<float4*>(out + base + 2 * stride) = v2;
    *reinterpret_cast<float4*>(out + base + 3 * stride) = v3;
}

extern "C" void kernel_launch(void* const* d_in, const int* in_sizes, int n_in,
                              void* d_out, int out_size)
{
    const float* x  = (const float*)d_in[0];
    const float* W1 = (const float*)d_in[1];
    const float* b1 = (const float*)d_in[2];
    const float* W2 = (const float*)d_in[3];
    const float* b2 = (const float*)d_in[4];
    const float* W3 = (const float*)d_in[5];
    const float* b3 = (const float*)d_in[6];
    float* out = (float*)d_out;

    dim3 blk(32, TY);
    k_forward<<<NBLKF, blk>>>(x, W1, b1, W2, b2, W3, b3, out);
    k_reduce<<<96, 256>>>();
    const int write_loss = (out_size > BATCH * SN) ? 1 : 0;
    k_stats<<<1, 32>>>(out, write_loss);
    k_norm<<<1024, 256>>>(out);
}